// round 11
// baseline (speedup 1.0000x reference)
#include <cuda_runtime.h>
#include <cuda_bf16.h>
#include <math.h>
#include <stdint.h>

#define BATCH 2
#define SEQ   2048
#define DIM   2048
#define NH    16
#define NKV   8
#define HD    128
#define KVD   (NKV*HD)
#define SK    64
#define INV_SQRT_HD 0.08838834764831845f  /* 1/sqrt(128) */

/* ------------------------- scratch (static device) ------------------------ */
__device__ float    g_AS [(size_t)3*BATCH*SEQ*SK];   /* ASq/ASk/ASv packed */
__device__ float    g_ASo[(size_t)BATCH*SEQ*SK];
__device__ float    g_Tq [(size_t)BATCH*DIM*SK];
__device__ float    g_Tk [(size_t)BATCH*KVD*SK];
__device__ float    g_Tv [(size_t)BATCH*KVD*SK];
__device__ float    g_To [(size_t)BATCH*DIM*SK];
__device__ float    g_q  [(size_t)BATCH*NH *SEQ*HD];
__device__ float    g_k  [(size_t)BATCH*NKV*SEQ*HD];
__device__ float    g_v  [(size_t)BATCH*NKV*SEQ*HD];
__device__ float    g_ao [(size_t)BATCH*SEQ*DIM];
/* pre-split sketch matrices, MMA-B layout: [which][b][n=64][k word] */
__device__ uint32_t g_SB [(size_t)4*BATCH*64*2048];

/* ---------------------- bf16 split / mma helpers ---------------------- */
__device__ __forceinline__ uint32_t pack_bf16(float a, float b) {
    __nv_bfloat162 t = __floats2bfloat162_rn(a, b);
    return *reinterpret_cast<uint32_t*>(&t);
}
/* 2-term bf16 split of a pair: (hi word, lo word), ~16-17 mantissa bits */
__device__ __forceinline__ void split2(float a, float b,
                                       uint32_t& hi, uint32_t& lo) {
    float ha = __bfloat162float(__float2bfloat16_rn(a));
    float hb = __bfloat162float(__float2bfloat16_rn(b));
    hi = pack_bf16(ha, hb);
    lo = pack_bf16(a - ha, b - hb);
}
__device__ __forceinline__ void mma_bf16(float* c, const uint32_t* a,
                                         uint32_t b0, uint32_t b1) {
    asm volatile(
        "mma.sync.aligned.m16n8k16.row.col.f32.bf16.bf16.f32 "
        "{%0,%1,%2,%3}, {%4,%5,%6,%7}, {%8,%9}, {%0,%1,%2,%3};"
        : "+f"(c[0]), "+f"(c[1]), "+f"(c[2]), "+f"(c[3])
        : "r"(a[0]), "r"(a[1]), "r"(a[2]), "r"(a[3]), "r"(b0), "r"(b1));
}
/* c += (ah+al)*(bh+bl) dropping al*bl; small terms first */
__device__ __forceinline__ void mma3b(float* c,
                                      const uint32_t* ah, const uint32_t* al,
                                      uint32_t bh0, uint32_t bh1,
                                      uint32_t bl0, uint32_t bl1) {
    mma_bf16(c, al, bh0, bh1);
    mma_bf16(c, ah, bl0, bl1);
    mma_bf16(c, ah, bh0, bh1);
}

/* =====================================================================
 * k_splitS: pre-split all four sketch matrices into MMA-B layout.
 *   g_SB[((which*BATCH+b)*64+n)*2048 + 2*jq + {0,1}] = bf16 hi/lo of
 *   S[b][2jq][n], S[b][2jq+1][n].  524288 items, grid 2048 x 256.
 * =====================================================================*/
__global__ void k_splitS(const float* __restrict__ Sq, const float* __restrict__ Sk,
                         const float* __restrict__ Sv, const float* __restrict__ So)
{
    int t = blockIdx.x*256 + threadIdx.x;
    int jq = t & 1023;
    int n  = (t >> 10) & 63;
    int b  = (t >> 16) & 1;
    int which = t >> 17;
    const float* S = (which==0?Sq:which==1?Sk:which==2?Sv:So) + (size_t)b*DIM*SK;
    float f0 = S[(size_t)(2*jq  )*SK + n];
    float f1 = S[(size_t)(2*jq+1)*SK + n];
    uint32_t hi, lo;
    split2(f0, f1, hi, lo);
    *(uint2*)(g_SB + (((size_t)which*BATCH + b)*64 + n)*2048 + (size_t)jq*2) =
        make_uint2(hi, lo);
}

/* =====================================================================
 * k_gemm_mma<NB>: C[wb] = alpha * A(Mx2048 row) @ B[wb]^T, N=64, via
 *   2-term bf16 split 3-MMA. 128x64 tile, 8 warps (16 rows each).
 *   A split per K-step into smem; B read pre-split from g_SB.
 *   NB=3 fuses the q/k/v sketch GEMMs (shared A).
 *   smem strides 40 words (==8 mod 32 -> conflict-free LDS.64).
 * =====================================================================*/
#define GAS 40
#define GEMM_SMEM(NB) ((128*GAS + (NB)*64*GAS) * 4)

template<int NB>
__global__ void __launch_bounds__(256, 1) k_gemm_mma(
    const float* __restrict__ A, long strideA,
    const uint32_t* __restrict__ B, long strideBb, long strideBw,
    float* __restrict__ C, long strideCb, long strideCw,
    float alpha)
{
    extern __shared__ uint32_t smg[];
    uint32_t* sA = smg;               /* [128][40] */
    uint32_t* sB = smg + 128*GAS;     /* [NB*64][40] */

    int b = blockIdx.z;
    int tm0 = blockIdx.x * 128;
    A += (size_t)b*strideA + (size_t)tm0*DIM;
    B += (size_t)b*strideBb;
    C += (size_t)b*strideCb + (size_t)tm0*SK;

    int tid = threadIdx.x, lane = tid & 31, w = tid >> 5;
    int gid = lane >> 2, qd = lane & 3;
    int m0 = w*16;
    int ar = tid >> 1, ahalf = tid & 1;

    float acc[NB][8][4] = {};

    for (int k0 = 0; k0 < DIM; k0 += 32) {
        /* stage loads in regs (overlap previous MMA) */
        float4 av[4];
        const float* Ap = A + (size_t)ar*DIM + k0 + ahalf*16;
        av[0] = ((const float4*)Ap)[0]; av[1] = ((const float4*)Ap)[1];
        av[2] = ((const float4*)Ap)[2]; av[3] = ((const float4*)Ap)[3];
        uint4 bv[NB][2];
        #pragma unroll
        for (int wb = 0; wb < NB; wb++)
            #pragma unroll
            for (int rep = 0; rep < 2; rep++) {
                int idx = rep*256 + tid;
                int n = idx >> 3, j4 = idx & 7;
                bv[wb][rep] = *(const uint4*)(B + (size_t)wb*strideBw
                                              + (size_t)n*2048 + k0 + j4*4);
            }
        __syncthreads();
        /* store A (split) */
        #pragma unroll
        for (int i = 0; i < 4; i++) {
            uint32_t h01, l01, h23, l23;
            split2(av[i].x, av[i].y, h01, l01);
            split2(av[i].z, av[i].w, h23, l23);
            *(uint4*)(sA + (size_t)ar*GAS + ahalf*16 + i*4) =
                make_uint4(h01, l01, h23, l23);
        }
        /* store B */
        #pragma unroll
        for (int wb = 0; wb < NB; wb++)
            #pragma unroll
            for (int rep = 0; rep < 2; rep++) {
                int idx = rep*256 + tid;
                int n = idx >> 3, j4 = idx & 7;
                *(uint4*)(sB + (size_t)(wb*64 + n)*GAS + j4*4) = bv[wb][rep];
            }
        __syncthreads();
        /* MMA */
        #pragma unroll
        for (int ks = 0; ks < 2; ks++) {
            uint2 qa0 = *(const uint2*)(sA + (size_t)(m0+gid  )*GAS + (8*ks+qd  )*2);
            uint2 qa1 = *(const uint2*)(sA + (size_t)(m0+gid+8)*GAS + (8*ks+qd  )*2);
            uint2 qa2 = *(const uint2*)(sA + (size_t)(m0+gid  )*GAS + (8*ks+qd+4)*2);
            uint2 qa3 = *(const uint2*)(sA + (size_t)(m0+gid+8)*GAS + (8*ks+qd+4)*2);
            uint32_t ah[4] = {qa0.x, qa1.x, qa2.x, qa3.x};
            uint32_t al[4] = {qa0.y, qa1.y, qa2.y, qa3.y};
            #pragma unroll
            for (int nt = 0; nt < 8; nt++)
                #pragma unroll
                for (int wb = 0; wb < NB; wb++) {
                    uint2 kb0 = *(const uint2*)(sB + (size_t)(wb*64+nt*8+gid)*GAS + (8*ks+qd  )*2);
                    uint2 kb1 = *(const uint2*)(sB + (size_t)(wb*64+nt*8+gid)*GAS + (8*ks+qd+4)*2);
                    mma3b(acc[wb][nt], ah, al, kb0.x, kb1.x, kb0.y, kb1.y);
                }
        }
    }
    /* epilogue */
    #pragma unroll
    for (int wb = 0; wb < NB; wb++) {
        float* Cw = C + (size_t)wb*strideCw;
        #pragma unroll
        for (int nt = 0; nt < 8; nt++) {
            int n = nt*8 + 2*qd;
            *(float2*)(Cw + (size_t)(m0+gid  )*SK + n) =
                make_float2(acc[wb][nt][0]*alpha, acc[wb][nt][1]*alpha);
            *(float2*)(Cw + (size_t)(m0+gid+8)*SK + n) =
                make_float2(acc[wb][nt][2]*alpha, acc[wb][nt][3]*alpha);
        }
    }
}

/* =====================================================================
 * k_proj: 64x64 tile of  X = AS (Sx64) @ T^T (64xM)   (K = 64, fp32)
 * =====================================================================*/
__global__ __launch_bounds__(256) void k_proj(const float* __restrict__ freqs,
                                              float* __restrict__ dout, int mode)
{
    int b  = blockIdx.z;
    int s0 = blockIdx.x * 64, m0 = blockIdx.y * 64;

    const float* ASp; const float* Tp;
    if      (mode == 0) { ASp = g_AS + ((size_t)0*BATCH + b)*SEQ*SK; Tp = g_Tq + (size_t)b*DIM*SK; }
    else if (mode == 1) { ASp = g_AS + ((size_t)1*BATCH + b)*SEQ*SK; Tp = g_Tk + (size_t)b*KVD*SK; }
    else if (mode == 2) { ASp = g_AS + ((size_t)2*BATCH + b)*SEQ*SK; Tp = g_Tv + (size_t)b*KVD*SK; }
    else                { ASp = g_ASo + (size_t)b*SEQ*SK;            Tp = g_To + (size_t)b*DIM*SK; }

    __shared__ float sA[64][68];
    __shared__ float sB[64][68];

    int tid = threadIdx.x, tx = tid & 15, ty = tid >> 4;

    #pragma unroll
    for (int it = 0; it < 4; it++) {
        int r  = (tid >> 4) + it*16;
        int c4 = (tid & 15) * 4;
        float4 a = *(const float4*)(ASp + (size_t)(s0 + r)*SK + c4);
        sA[c4+0][r]=a.x; sA[c4+1][r]=a.y; sA[c4+2][r]=a.z; sA[c4+3][r]=a.w;
        float4 t = *(const float4*)(Tp  + (size_t)(m0 + r)*SK + c4);
        sB[c4+0][r]=t.x; sB[c4+1][r]=t.y; sB[c4+2][r]=t.z; sB[c4+3][r]=t.w;
    }
    __syncthreads();

    float acc[4][4] = {};
    #pragma unroll
    for (int k = 0; k < 64; k++) {
        float4 a  = *(const float4*)&sA[k][ty*4];
        float4 bb = *(const float4*)&sB[k][tx*4];
        acc[0][0]+=a.x*bb.x; acc[0][1]+=a.x*bb.y; acc[0][2]+=a.x*bb.z; acc[0][3]+=a.x*bb.w;
        acc[1][0]+=a.y*bb.x; acc[1][1]+=a.y*bb.y; acc[1][2]+=a.y*bb.z; acc[1][3]+=a.y*bb.w;
        acc[2][0]+=a.z*bb.x; acc[2][1]+=a.z*bb.y; acc[2][2]+=a.z*bb.z; acc[2][3]+=a.z*bb.w;
        acc[3][0]+=a.w*bb.x; acc[3][1]+=a.w*bb.y; acc[3][2]+=a.w*bb.z; acc[3][3]+=a.w*bb.w;
    }

    if (mode == 3) {
        #pragma unroll
        for (int i = 0; i < 4; i++) {
            *(float4*)(dout + ((size_t)b*SEQ + s0 + ty*4 + i)*DIM + m0 + tx*4) =
                make_float4(acc[i][0], acc[i][1], acc[i][2], acc[i][3]);
        }
    } else if (mode == 2) {
        int h  = m0 >> 7;
        int d0 = (m0 & 127) + tx*4;
        float* base = g_v + ((size_t)(b*NKV + h))*SEQ*HD;
        #pragma unroll
        for (int i = 0; i < 4; i++) {
            *(float4*)(base + (size_t)(s0 + ty*4 + i)*HD + d0) =
                make_float4(acc[i][0], acc[i][1], acc[i][2], acc[i][3]);
        }
    } else {
        int h  = m0 >> 7;
        int d0 = (m0 & 127) + tx*4;
        int dh = d0 >> 1;
        float* base = (mode == 0) ? g_q + ((size_t)(b*NH  + h))*SEQ*HD
                                  : g_k + ((size_t)(b*NKV + h))*SEQ*HD;
        #pragma unroll
        for (int i = 0; i < 4; i++) {
            int srow = s0 + ty*4 + i;
            const float* f = freqs + ((size_t)srow*64 + dh)*2;
            float c0 = f[0], n0 = f[1], c1 = f[2], n1 = f[3];
            float e0 = acc[i][0]*n0 - acc[i][1]*c0;
            float o0 = acc[i][0]*c0 + acc[i][1]*n0;
            float e1 = acc[i][2]*n1 - acc[i][3]*c1;
            float o1 = acc[i][2]*c1 + acc[i][3]*n1;
            *(float4*)(base + (size_t)srow*HD + d0) = make_float4(e0, o0, e1, o1);
        }
    }
}

/* =====================================================================
 * k_flash: causal flash attention, 2-term bf16 split, mma m16n8k16.
 *   (unchanged from round 10)
 * =====================================================================*/
#define QS 136
#define KS 136
#define VS 72
#define PS 72
#define STS_ 132
#define SQ_OFF  0
#define SK_OFF  (128*QS)
#define SV_OFF  (SK_OFF + 64*KS)
#define SP_OFF  (SV_OFF + 128*VS)
#define STG_OFF SP_OFF
#define FLASH_WORDS (SP_OFF + 128*PS)
#define FLASH_SMEM  (FLASH_WORDS * 4)

__global__ void __launch_bounds__(256, 1) k_flash()
{
    extern __shared__ uint32_t smw[];
    uint32_t* sQ = smw + SQ_OFF;
    uint32_t* sK = smw + SK_OFF;
    uint32_t* sV = smw + SV_OFF;
    uint32_t* sP = smw + SP_OFF;
    float*    stF = (float*)(smw + STG_OFF);

    int tid = threadIdx.x, lane = tid & 31, w = tid >> 5;
    int qt = (int)gridDim.x - 1 - (int)blockIdx.x;
    int h = blockIdx.y, b = blockIdx.z;
    int gid = lane >> 2, qd = lane & 3;

    const float* Qg = g_q + ((size_t)(b*NH  + h))     *SEQ*HD + (size_t)qt*128*HD;
    const float* Kb = g_k + ((size_t)(b*NKV + (h>>1)))*SEQ*HD;
    const float* Vb = g_v + ((size_t)(b*NKV + (h>>1)))*SEQ*HD;

    #pragma unroll
    for (int it = 0; it < 16; it++) {
        int slot = tid + it*256;
        int r = slot >> 5, c4 = (slot & 31) * 4;
        float4 v = *(const float4*)(Qg + (size_t)r*HD + c4);
        uint32_t h01, l01, h23, l23;
        split2(v.x*INV_SQRT_HD, v.y*INV_SQRT_HD, h01, l01);
        split2(v.z*INV_SQRT_HD, v.w*INV_SQRT_HD, h23, l23);
        *(uint4*)(sQ + (size_t)r*QS + c4) = make_uint4(h01, l01, h23, l23);
    }

    int m0 = w*16;
    float o[16][4] = {};
    float miA = -1e30f, miB = -1e30f, liA = 0.f, liB = 0.f;
    int row_min = qt*128 + w*16;
    int row_max = row_min + 15;
    int nkt = 2*qt + 2;

    for (int kt = 0; kt < nkt; kt++) {
        const float* Kg = Kb + (size_t)kt*64*HD;
        const float* Vg = Vb + (size_t)kt*64*HD;
        #pragma unroll
        for (int it = 0; it < 8; it++) {
            int slot = tid + it*256;
            int r = slot >> 5, c4 = (slot & 31) * 4;
            float4 kv = *(const float4*)(Kg + (size_t)r*HD + c4);
            uint32_t h01, l01, h23, l23;
            split2(kv.x, kv.y, h01, l01);
            split2(kv.z, kv.w, h23, l23);
            *(uint4*)(sK + (size_t)r*KS + c4) = make_uint4(h01, l01, h23, l23);
            float4 vv = *(const float4*)(Vg + (size_t)r*HD + c4);
            *(float4*)(stF + (size_t)r*STS_ + c4) = vv;
        }
        __syncthreads();

        #pragma unroll
        for (int it = 0; it < 16; it++) {
            int t = tid + it*256;
            int d  = t & 127;
            int pj = t >> 7;
            float f0 = stF[(size_t)(2*pj    )*STS_ + d];
            float f1 = stF[(size_t)(2*pj + 1)*STS_ + d];
            uint32_t hi, lo;
            split2(f0, f1, hi, lo);
            *(uint2*)(sV + (size_t)d*VS + pj*2) = make_uint2(hi, lo);
        }

        bool active = (kt*64 <= row_max);
        float s[8][4] = {};
        if (active) {
            #pragma unroll
            for (int ks = 0; ks < 8; ks++) {
                uint2 qa0 = *(const uint2*)(sQ + (size_t)(m0+gid  )*QS + (8*ks+qd  )*2);
                uint2 qa1 = *(const uint2*)(sQ + (size_t)(m0+gid+8)*QS + (8*ks+qd  )*2);
                uint2 qa2 = *(const uint2*)(sQ + (size_t)(m0+gid  )*QS + (8*ks+qd+4)*2);
                uint2 qa3 = *(const uint2*)(sQ + (size_t)(m0+gid+8)*QS + (8*ks+qd+4)*2);
                uint32_t ah[4] = {qa0.x, qa1.x, qa2.x, qa3.x};
                uint32_t al[4] = {qa0.y, qa1.y, qa2.y, qa3.y};
                #pragma unroll
                for (int nt = 0; nt < 8; nt++) {
                    uint2 kb0 = *(const uint2*)(sK + (size_t)(nt*8+gid)*KS + (8*ks+qd  )*2);
                    uint2 kb1 = *(const uint2*)(sK + (size_t)(nt*8+gid)*KS + (8*ks+qd+4)*2);
                    mma3b(s[nt], ah, al, kb0.x, kb1.x, kb0.y, kb1.y);
                }
            }

            if (kt*64 + 63 > row_min) {
                int rA = row_min + gid, rB = rA + 8;
                #pragma unroll
                for (int nt = 0; nt < 8; nt++) {
                    int c0 = kt*64 + nt*8 + 2*qd;
                    if (c0     > rA) s[nt][0] = -1e30f;
                    if (c0 + 1 > rA) s[nt][1] = -1e30f;
                    if (c0     > rB) s[nt][2] = -1e30f;
                    if (c0 + 1 > rB) s[nt][3] = -1e30f;
                }
            }

            float mA = -1e30f, mB = -1e30f;
            #pragma unroll
            for (int nt = 0; nt < 8; nt++) {
                mA = fmaxf(mA, fmaxf(s[nt][0], s[nt][1]));
                mB = fmaxf(mB, fmaxf(s[nt][2], s[nt][3]));
            }
            mA = fmaxf(mA, __shfl_xor_sync(0xffffffffu, mA, 1));
            mA = fmaxf(mA, __shfl_xor_sync(0xffffffffu, mA, 2));
            mB = fmaxf(mB, __shfl_xor_sync(0xffffffffu, mB, 1));
            mB = fmaxf(mB, __shfl_xor_sync(0xffffffffu, mB, 2));
            float newmA = fmaxf(miA, mA), newmB = fmaxf(miB, mB);
            float alA = __expf(miA - newmA), alB = __expf(miB - newmB);
            float sumA = 0.f, sumB = 0.f;
            #pragma unroll
            for (int nt = 0; nt < 8; nt++) {
                s[nt][0] = __expf(s[nt][0] - newmA);
                s[nt][1] = __expf(s[nt][1] - newmA);
                s[nt][2] = __expf(s[nt][2] - newmB);
                s[nt][3] = __expf(s[nt][3] - newmB);
                sumA += s[nt][0] + s[nt][1];
                sumB += s[nt][2] + s[nt][3];
            }
            sumA += __shfl_xor_sync(0xffffffffu, sumA, 1);
            sumA += __shfl_xor_sync(0xffffffffu, sumA, 2);
            sumB += __shfl_xor_sync(0xffffffffu, sumB, 1);
            sumB += __shfl_xor_sync(0xffffffffu, sumB, 2);
            liA = liA*alA + sumA;  miA = newmA;
            liB = liB*alB + sumB;  miB = newmB;

            #pragma unroll
            for (int nt = 0; nt < 16; nt++) {
                o[nt][0] *= alA; o[nt][1] *= alA;
                o[nt][2] *= alB; o[nt][3] *= alB;
            }
        }
        __syncthreads();

        if (active) {
            #pragma unroll
            for (int nt = 0; nt < 8; nt++) {
                uint32_t hA, lA, hB, lB;
                split2(s[nt][0], s[nt][1], hA, lA);
                split2(s[nt][2], s[nt][3], hB, lB);
                *(uint2*)(sP + (size_t)(m0+gid  )*PS + (nt*4+qd)*2) = make_uint2(hA, lA);
                *(uint2*)(sP + (size_t)(m0+gid+8)*PS + (nt*4+qd)*2) = make_uint2(hB, lB);
            }
            __syncwarp();

            #pragma unroll
            for (int ks = 0; ks < 4; ks++) {
                uint2 pa0 = *(const uint2*)(sP + (size_t)(m0+gid  )*PS + (8*ks+qd  )*2);
                uint2 pa1 = *(const uint2*)(sP + (size_t)(m0+gid+8)*PS + (8*ks+qd  )*2);
                uint2 pa2 = *(const uint2*)(sP + (size_t)(m0+gid  )*PS + (8*ks+qd+4)*2);
                uint2 pa3 = *(const uint2*)(sP + (size_t)(m0+gid+8)*PS + (8*ks+qd+4)*2);
                uint32_t ph[4] = {pa0.x, pa1.x, pa2.x, pa3.x};
                uint32_t pl[4] = {pa0.y, pa1.y, pa2.y, pa3.y};
                #pragma unroll
                for (int nt = 0; nt < 16; nt++) {
                    uint2 vb0 = *(const uint2*)(sV + (size_t)(nt*8+gid)*VS + (8*ks+qd  )*2);
                    uint2 vb1 = *(const uint2*)(sV + (size_t)(nt*8+gid)*VS + (8*ks+qd+4)*2);
                    mma3b(o[nt], ph, pl, vb0.x, vb1.x, vb0.y, vb1.y);
                }
            }
        }
        __syncthreads();
    }

    float invA = 1.0f / liA, invB = 1.0f / liB;
    float* Og = g_ao + ((size_t)b*SEQ + (size_t)qt*128)*DIM + (size_t)h*HD;
    #pragma unroll
    for (int nt = 0; nt < 16; nt++) {
        int c = nt*8 + 2*qd;
        float2 vA = make_float2(o[nt][0]*invA, o[nt][1]*invA);
        float2 vB = make_float2(o[nt][2]*invB, o[nt][3]*invB);
        *(float2*)(Og + (size_t)(m0 + gid)    *DIM + c) = vA;
        *(float2*)(Og + (size_t)(m0 + gid + 8)*DIM + c) = vB;
    }
}

/* ========================= launch ========================= */
extern "C" void kernel_launch(void* const* d_in, const int* in_sizes, int n_in,
                              void* d_out, int out_size)
{
    const float* x  = (const float*)d_in[0];
    const float* wq = (const float*)d_in[1];
    const float* wk = (const float*)d_in[2];
    const float* wv = (const float*)d_in[3];
    const float* wo = (const float*)d_in[4];
    const float* Sq = (const float*)d_in[5];
    const float* Sk = (const float*)d_in[6];
    const float* Sv = (const float*)d_in[7];
    const float* So = (const float*)d_in[8];
    const float* fr = (const float*)d_in[9];
    float* out = (float*)d_out;

    cudaFuncSetAttribute(k_flash, cudaFuncAttributeMaxDynamicSharedMemorySize,
                         FLASH_SMEM);
    cudaFuncSetAttribute(k_gemm_mma<3>, cudaFuncAttributeMaxDynamicSharedMemorySize,
                         GEMM_SMEM(3));
    cudaFuncSetAttribute(k_gemm_mma<1>, cudaFuncAttributeMaxDynamicSharedMemorySize,
                         GEMM_SMEM(1));

    /* device-symbol addresses (host-side) */
    uint32_t* dSB;  cudaGetSymbolAddress((void**)&dSB,  g_SB);
    float*    dAS;  cudaGetSymbolAddress((void**)&dAS,  g_AS);
    float*    dASo; cudaGetSymbolAddress((void**)&dASo, g_ASo);
    float*    dTq;  cudaGetSymbolAddress((void**)&dTq,  g_Tq);
    float*    dTk;  cudaGetSymbolAddress((void**)&dTk,  g_Tk);
    float*    dTv;  cudaGetSymbolAddress((void**)&dTv,  g_Tv);
    float*    dTo;  cudaGetSymbolAddress((void**)&dTo,  g_To);
    float*    dAo;  cudaGetSymbolAddress((void**)&dAo,  g_ao);

    dim3 blk(256);
    const long SBw = 64L*2048;             /* words per (which,b) B matrix */
    const long SBwb = (long)BATCH*SBw;     /* words per which */

    /* pre-split sketches into MMA-B layout */
    k_splitS<<<2048, blk>>>(Sq, Sk, Sv, So);

    /* AS_{q,k,v} = x @ S / 64  (fused, NB=3) */
    k_gemm_mma<3><<<dim3(16,1,BATCH), blk, GEMM_SMEM(3)>>>(
        x, (long)SEQ*DIM, dSB, SBw, SBwb,
        dAS, (long)SEQ*SK, (long)BATCH*SEQ*SK, 1.0f/SK);

    /* T_{q,k,v,o} = w @ S */
    k_gemm_mma<1><<<dim3(16,1,BATCH), blk, GEMM_SMEM(1)>>>(
        wq, 0L, dSB + 0*SBwb, SBw, 0L, dTq, (long)DIM*SK, 0L, 1.0f);
    k_gemm_mma<1><<<dim3( 8,1,BATCH), blk, GEMM_SMEM(1)>>>(
        wk, 0L, dSB + 1*SBwb, SBw, 0L, dTk, (long)KVD*SK, 0L, 1.0f);
    k_gemm_mma<1><<<dim3( 8,1,BATCH), blk, GEMM_SMEM(1)>>>(
        wv, 0L, dSB + 2*SBwb, SBw, 0L, dTv, (long)KVD*SK, 0L, 1.0f);
    k_gemm_mma<1><<<dim3(16,1,BATCH), blk, GEMM_SMEM(1)>>>(
        wo, 0L, dSB + 3*SBwb, SBw, 0L, dTo, (long)DIM*SK, 0L, 1.0f);

    /* q/k/v projections (+RoPE, layout to [b,h,s,d]) */
    k_proj<<<dim3(32, 32, BATCH), blk>>>(fr, out, 0);
    k_proj<<<dim3(32, 16, BATCH), blk>>>(fr, out, 1);
    k_proj<<<dim3(32, 16, BATCH), blk>>>(fr, out, 2);

    /* causal flash attention (2-term bf16 split, m16n8k16) -> g_ao */
    k_flash<<<dim3(SEQ/128, NH, BATCH), blk, FLASH_SMEM>>>();

    /* AS_o = attn_out @ So / 64 */
    k_gemm_mma<1><<<dim3(16,1,BATCH), blk, GEMM_SMEM(1)>>>(
        dAo, (long)SEQ*DIM, dSB + 3*SBwb, SBw, 0L,
        dASo, (long)SEQ*SK, 0L, 1.0f/SK);

    /* final = AS_o @ To^T -> d_out */
    k_proj<<<dim3(32, 32, BATCH), blk>>>(fr, out, 3);
}

// round 12
// speedup vs baseline: 1.5839x; 1.5839x over previous
#include <cuda_runtime.h>
#include <cuda_bf16.h>
#include <math.h>
#include <stdint.h>

#define BATCH 2
#define SEQ   2048
#define DIM   2048
#define NH    16
#define NKV   8
#define HD    128
#define KVD   (NKV*HD)
#define SK    64
#define INV_SQRT_HD 0.08838834764831845f  /* 1/sqrt(128) */

/* ------------------------- scratch (static device) ------------------------ */
__device__ float    g_AS [(size_t)3*BATCH*SEQ*SK];   /* ASq/ASk/ASv packed */
__device__ float    g_ASo[(size_t)BATCH*SEQ*SK];
__device__ float    g_Tq [(size_t)BATCH*DIM*SK];
__device__ float    g_Tk [(size_t)BATCH*KVD*SK];
__device__ float    g_Tv [(size_t)BATCH*KVD*SK];
__device__ float    g_To [(size_t)BATCH*DIM*SK];
__device__ float    g_q  [(size_t)BATCH*NH *SEQ*HD];
__device__ float    g_k  [(size_t)BATCH*NKV*SEQ*HD];
__device__ float    g_v  [(size_t)BATCH*NKV*SEQ*HD];
__device__ float    g_ao [(size_t)BATCH*SEQ*DIM];
/* pre-split sketch matrices, MMA-B layout: [which][b][n=64][k word] */
__device__ uint32_t g_SB [(size_t)4*BATCH*64*2048];

/* ---------------------- bf16 split / mma helpers ---------------------- */
__device__ __forceinline__ uint32_t pack_bf16(float a, float b) {
    __nv_bfloat162 t = __floats2bfloat162_rn(a, b);
    return *reinterpret_cast<uint32_t*>(&t);
}
/* 2-term bf16 split of a pair: (hi word, lo word), ~16-17 mantissa bits */
__device__ __forceinline__ void split2(float a, float b,
                                       uint32_t& hi, uint32_t& lo) {
    float ha = __bfloat162float(__float2bfloat16_rn(a));
    float hb = __bfloat162float(__float2bfloat16_rn(b));
    hi = pack_bf16(ha, hb);
    lo = pack_bf16(a - ha, b - hb);
}
__device__ __forceinline__ void mma_bf16(float* c, const uint32_t* a,
                                         uint32_t b0, uint32_t b1) {
    asm volatile(
        "mma.sync.aligned.m16n8k16.row.col.f32.bf16.bf16.f32 "
        "{%0,%1,%2,%3}, {%4,%5,%6,%7}, {%8,%9}, {%0,%1,%2,%3};"
        : "+f"(c[0]), "+f"(c[1]), "+f"(c[2]), "+f"(c[3])
        : "r"(a[0]), "r"(a[1]), "r"(a[2]), "r"(a[3]), "r"(b0), "r"(b1));
}
/* c += (ah+al)*(bh+bl) dropping al*bl; small terms first */
__device__ __forceinline__ void mma3b(float* c,
                                      const uint32_t* ah, const uint32_t* al,
                                      uint32_t bh0, uint32_t bh1,
                                      uint32_t bl0, uint32_t bl1) {
    mma_bf16(c, al, bh0, bh1);
    mma_bf16(c, ah, bl0, bl1);
    mma_bf16(c, ah, bh0, bh1);
}

/* =====================================================================
 * k_splitS: pre-split all four sketch matrices into MMA-B layout.
 * =====================================================================*/
__global__ void k_splitS(const float* __restrict__ Sq, const float* __restrict__ Sk,
                         const float* __restrict__ Sv, const float* __restrict__ So)
{
    int t = blockIdx.x*256 + threadIdx.x;
    int jq = t & 1023;
    int n  = (t >> 10) & 63;
    int b  = (t >> 16) & 1;
    int which = t >> 17;
    const float* S = (which==0?Sq:which==1?Sk:which==2?Sv:So) + (size_t)b*DIM*SK;
    float f0 = S[(size_t)(2*jq  )*SK + n];
    float f1 = S[(size_t)(2*jq+1)*SK + n];
    uint32_t hi, lo;
    split2(f0, f1, hi, lo);
    *(uint2*)(g_SB + (((size_t)which*BATCH + b)*64 + n)*2048 + (size_t)jq*2) =
        make_uint2(hi, lo);
}

/* =====================================================================
 * k_gemm_mma: multi-job GEMM, C = alpha * A(Mx2048) @ B^T (N=64).
 *   2-term bf16 split, 3x mma m16n8k16. 128x64 tile, 8 warps.
 *   Double-buffered smem, register prefetch of next K-chunk (32 elems)
 *   so LDG latency hides under the MMA stream. One sync per K-chunk.
 *   Job table passed by value; grid (mtile, job, batch).
 * =====================================================================*/
#define GAS 40
#define GBUF ((128 + 64) * GAS)        /* words per buffer = 7680 */
#define GEMM_SMEM (2 * GBUF * 4)       /* 61440 B */

struct GemmJobs {
    const float*    A[7];
    const uint32_t* B[7];
    float*          C[7];
    long  sAb[7];
    long  sBb[7];
    long  sCb[7];
    int   mtiles[7];
    float alpha[7];
};

__global__ void __launch_bounds__(256, 1) k_gemm_mma(GemmJobs J)
{
    extern __shared__ uint32_t smg[];
    int job = blockIdx.y, b = blockIdx.z;
    if ((int)blockIdx.x >= J.mtiles[job]) return;
    int tm0 = blockIdx.x * 128;
    const float*    A = J.A[job] + (size_t)b*J.sAb[job] + (size_t)tm0*DIM;
    const uint32_t* B = J.B[job] + (size_t)b*J.sBb[job];
    float*          C = J.C[job] + (size_t)b*J.sCb[job] + (size_t)tm0*SK;
    float alpha = J.alpha[job];

    int tid = threadIdx.x, lane = tid & 31, w = tid >> 5;
    int gid = lane >> 2, qd = lane & 3;
    int m0 = w*16;
    int ar = tid >> 1, ahalf = tid & 1;
    int bn = tid >> 3, bj4 = tid & 7;          /* B-load coords (rep via +32 n) */

    float acc[8][4] = {};
    float4 av[4];
    uint4  bv[2];

    /* ---- preload chunk 0 ---- */
    {
        const float* Ap = A + (size_t)ar*DIM + ahalf*16;
        av[0] = ((const float4*)Ap)[0]; av[1] = ((const float4*)Ap)[1];
        av[2] = ((const float4*)Ap)[2]; av[3] = ((const float4*)Ap)[3];
        bv[0] = *(const uint4*)(B + (size_t)bn*2048 + bj4*4);
        bv[1] = *(const uint4*)(B + (size_t)(bn+32)*2048 + bj4*4);
    }
    /* ---- store chunk 0 to buffer 0 ---- */
    {
        uint32_t* dA = smg;
        uint32_t* dB = smg + 128*GAS;
        #pragma unroll
        for (int i = 0; i < 4; i++) {
            uint32_t h01, l01, h23, l23;
            split2(av[i].x, av[i].y, h01, l01);
            split2(av[i].z, av[i].w, h23, l23);
            *(uint4*)(dA + (size_t)ar*GAS + ahalf*16 + i*4) =
                make_uint4(h01, l01, h23, l23);
        }
        *(uint4*)(dB + (size_t)bn*GAS + bj4*4)      = bv[0];
        *(uint4*)(dB + (size_t)(bn+32)*GAS + bj4*4) = bv[1];
    }
    __syncthreads();

    for (int it = 0; it < 64; it++) {
        uint32_t* sA = smg + (it & 1)*GBUF;
        uint32_t* sB = sA + 128*GAS;
        bool more = (it + 1 < 64);
        if (more) {   /* prefetch next chunk into regs (overlaps MMA below) */
            int k0 = (it + 1)*32;
            const float* Ap = A + (size_t)ar*DIM + k0 + ahalf*16;
            av[0] = ((const float4*)Ap)[0]; av[1] = ((const float4*)Ap)[1];
            av[2] = ((const float4*)Ap)[2]; av[3] = ((const float4*)Ap)[3];
            bv[0] = *(const uint4*)(B + (size_t)bn*2048 + k0 + bj4*4);
            bv[1] = *(const uint4*)(B + (size_t)(bn+32)*2048 + k0 + bj4*4);
        }
        /* ---- MMA on current buffer ---- */
        #pragma unroll
        for (int ks = 0; ks < 2; ks++) {
            uint2 qa0 = *(const uint2*)(sA + (size_t)(m0+gid  )*GAS + (8*ks+qd  )*2);
            uint2 qa1 = *(const uint2*)(sA + (size_t)(m0+gid+8)*GAS + (8*ks+qd  )*2);
            uint2 qa2 = *(const uint2*)(sA + (size_t)(m0+gid  )*GAS + (8*ks+qd+4)*2);
            uint2 qa3 = *(const uint2*)(sA + (size_t)(m0+gid+8)*GAS + (8*ks+qd+4)*2);
            uint32_t ah[4] = {qa0.x, qa1.x, qa2.x, qa3.x};
            uint32_t al[4] = {qa0.y, qa1.y, qa2.y, qa3.y};
            #pragma unroll
            for (int nt = 0; nt < 8; nt++) {
                uint2 kb0 = *(const uint2*)(sB + (size_t)(nt*8+gid)*GAS + (8*ks+qd  )*2);
                uint2 kb1 = *(const uint2*)(sB + (size_t)(nt*8+gid)*GAS + (8*ks+qd+4)*2);
                mma3b(acc[nt], ah, al, kb0.x, kb1.x, kb0.y, kb1.y);
            }
        }
        if (more) {   /* store prefetched chunk to the other buffer */
            uint32_t* dA = smg + ((it + 1) & 1)*GBUF;
            uint32_t* dB = dA + 128*GAS;
            #pragma unroll
            for (int i = 0; i < 4; i++) {
                uint32_t h01, l01, h23, l23;
                split2(av[i].x, av[i].y, h01, l01);
                split2(av[i].z, av[i].w, h23, l23);
                *(uint4*)(dA + (size_t)ar*GAS + ahalf*16 + i*4) =
                    make_uint4(h01, l01, h23, l23);
            }
            *(uint4*)(dB + (size_t)bn*GAS + bj4*4)      = bv[0];
            *(uint4*)(dB + (size_t)(bn+32)*GAS + bj4*4) = bv[1];
            __syncthreads();
        }
    }

    /* ---- epilogue ---- */
    #pragma unroll
    for (int nt = 0; nt < 8; nt++) {
        int n = nt*8 + 2*qd;
        *(float2*)(C + (size_t)(m0+gid  )*SK + n) =
            make_float2(acc[nt][0]*alpha, acc[nt][1]*alpha);
        *(float2*)(C + (size_t)(m0+gid+8)*SK + n) =
            make_float2(acc[nt][2]*alpha, acc[nt][3]*alpha);
    }
}

/* =====================================================================
 * k_proj: 64x64 tile of  X = AS (Sx64) @ T^T (64xM)   (K = 64, fp32)
 * =====================================================================*/
__global__ __launch_bounds__(256) void k_proj(const float* __restrict__ freqs,
                                              float* __restrict__ dout, int mode)
{
    int b  = blockIdx.z;
    int s0 = blockIdx.x * 64, m0 = blockIdx.y * 64;

    const float* ASp; const float* Tp;
    if      (mode == 0) { ASp = g_AS + ((size_t)0*BATCH + b)*SEQ*SK; Tp = g_Tq + (size_t)b*DIM*SK; }
    else if (mode == 1) { ASp = g_AS + ((size_t)1*BATCH + b)*SEQ*SK; Tp = g_Tk + (size_t)b*KVD*SK; }
    else if (mode == 2) { ASp = g_AS + ((size_t)2*BATCH + b)*SEQ*SK; Tp = g_Tv + (size_t)b*KVD*SK; }
    else                { ASp = g_ASo + (size_t)b*SEQ*SK;            Tp = g_To + (size_t)b*DIM*SK; }

    __shared__ float sA[64][68];
    __shared__ float sB[64][68];

    int tid = threadIdx.x, tx = tid & 15, ty = tid >> 4;

    #pragma unroll
    for (int it = 0; it < 4; it++) {
        int r  = (tid >> 4) + it*16;
        int c4 = (tid & 15) * 4;
        float4 a = *(const float4*)(ASp + (size_t)(s0 + r)*SK + c4);
        sA[c4+0][r]=a.x; sA[c4+1][r]=a.y; sA[c4+2][r]=a.z; sA[c4+3][r]=a.w;
        float4 t = *(const float4*)(Tp  + (size_t)(m0 + r)*SK + c4);
        sB[c4+0][r]=t.x; sB[c4+1][r]=t.y; sB[c4+2][r]=t.z; sB[c4+3][r]=t.w;
    }
    __syncthreads();

    float acc[4][4] = {};
    #pragma unroll
    for (int k = 0; k < 64; k++) {
        float4 a  = *(const float4*)&sA[k][ty*4];
        float4 bb = *(const float4*)&sB[k][tx*4];
        acc[0][0]+=a.x*bb.x; acc[0][1]+=a.x*bb.y; acc[0][2]+=a.x*bb.z; acc[0][3]+=a.x*bb.w;
        acc[1][0]+=a.y*bb.x; acc[1][1]+=a.y*bb.y; acc[1][2]+=a.y*bb.z; acc[1][3]+=a.y*bb.w;
        acc[2][0]+=a.z*bb.x; acc[2][1]+=a.z*bb.y; acc[2][2]+=a.z*bb.z; acc[2][3]+=a.z*bb.w;
        acc[3][0]+=a.w*bb.x; acc[3][1]+=a.w*bb.y; acc[3][2]+=a.w*bb.z; acc[3][3]+=a.w*bb.w;
    }

    if (mode == 3) {
        #pragma unroll
        for (int i = 0; i < 4; i++) {
            *(float4*)(dout + ((size_t)b*SEQ + s0 + ty*4 + i)*DIM + m0 + tx*4) =
                make_float4(acc[i][0], acc[i][1], acc[i][2], acc[i][3]);
        }
    } else if (mode == 2) {
        int h  = m0 >> 7;
        int d0 = (m0 & 127) + tx*4;
        float* base = g_v + ((size_t)(b*NKV + h))*SEQ*HD;
        #pragma unroll
        for (int i = 0; i < 4; i++) {
            *(float4*)(base + (size_t)(s0 + ty*4 + i)*HD + d0) =
                make_float4(acc[i][0], acc[i][1], acc[i][2], acc[i][3]);
        }
    } else {
        int h  = m0 >> 7;
        int d0 = (m0 & 127) + tx*4;
        int dh = d0 >> 1;
        float* base = (mode == 0) ? g_q + ((size_t)(b*NH  + h))*SEQ*HD
                                  : g_k + ((size_t)(b*NKV + h))*SEQ*HD;
        #pragma unroll
        for (int i = 0; i < 4; i++) {
            int srow = s0 + ty*4 + i;
            const float* f = freqs + ((size_t)srow*64 + dh)*2;
            float c0 = f[0], n0 = f[1], c1 = f[2], n1 = f[3];
            float e0 = acc[i][0]*n0 - acc[i][1]*c0;
            float o0 = acc[i][0]*c0 + acc[i][1]*n0;
            float e1 = acc[i][2]*n1 - acc[i][3]*c1;
            float o1 = acc[i][2]*c1 + acc[i][3]*n1;
            *(float4*)(base + (size_t)srow*HD + d0) = make_float4(e0, o0, e1, o1);
        }
    }
}

/* =====================================================================
 * k_flash: causal flash attention, 2-term bf16 split, mma m16n8k16.
 *   (unchanged from round 10)
 * =====================================================================*/
#define QS 136
#define KS 136
#define VS 72
#define PS 72
#define STS_ 132
#define SQ_OFF  0
#define SK_OFF  (128*QS)
#define SV_OFF  (SK_OFF + 64*KS)
#define SP_OFF  (SV_OFF + 128*VS)
#define STG_OFF SP_OFF
#define FLASH_WORDS (SP_OFF + 128*PS)
#define FLASH_SMEM  (FLASH_WORDS * 4)

__global__ void __launch_bounds__(256, 1) k_flash()
{
    extern __shared__ uint32_t smw[];
    uint32_t* sQ = smw + SQ_OFF;
    uint32_t* sK = smw + SK_OFF;
    uint32_t* sV = smw + SV_OFF;
    uint32_t* sP = smw + SP_OFF;
    float*    stF = (float*)(smw + STG_OFF);

    int tid = threadIdx.x, lane = tid & 31, w = tid >> 5;
    int qt = (int)gridDim.x - 1 - (int)blockIdx.x;
    int h = blockIdx.y, b = blockIdx.z;
    int gid = lane >> 2, qd = lane & 3;

    const float* Qg = g_q + ((size_t)(b*NH  + h))     *SEQ*HD + (size_t)qt*128*HD;
    const float* Kb = g_k + ((size_t)(b*NKV + (h>>1)))*SEQ*HD;
    const float* Vb = g_v + ((size_t)(b*NKV + (h>>1)))*SEQ*HD;

    #pragma unroll
    for (int it = 0; it < 16; it++) {
        int slot = tid + it*256;
        int r = slot >> 5, c4 = (slot & 31) * 4;
        float4 v = *(const float4*)(Qg + (size_t)r*HD + c4);
        uint32_t h01, l01, h23, l23;
        split2(v.x*INV_SQRT_HD, v.y*INV_SQRT_HD, h01, l01);
        split2(v.z*INV_SQRT_HD, v.w*INV_SQRT_HD, h23, l23);
        *(uint4*)(sQ + (size_t)r*QS + c4) = make_uint4(h01, l01, h23, l23);
    }

    int m0 = w*16;
    float o[16][4] = {};
    float miA = -1e30f, miB = -1e30f, liA = 0.f, liB = 0.f;
    int row_min = qt*128 + w*16;
    int row_max = row_min + 15;
    int nkt = 2*qt + 2;

    for (int kt = 0; kt < nkt; kt++) {
        const float* Kg = Kb + (size_t)kt*64*HD;
        const float* Vg = Vb + (size_t)kt*64*HD;
        #pragma unroll
        for (int it = 0; it < 8; it++) {
            int slot = tid + it*256;
            int r = slot >> 5, c4 = (slot & 31) * 4;
            float4 kv = *(const float4*)(Kg + (size_t)r*HD + c4);
            uint32_t h01, l01, h23, l23;
            split2(kv.x, kv.y, h01, l01);
            split2(kv.z, kv.w, h23, l23);
            *(uint4*)(sK + (size_t)r*KS + c4) = make_uint4(h01, l01, h23, l23);
            float4 vv = *(const float4*)(Vg + (size_t)r*HD + c4);
            *(float4*)(stF + (size_t)r*STS_ + c4) = vv;
        }
        __syncthreads();

        #pragma unroll
        for (int it = 0; it < 16; it++) {
            int t = tid + it*256;
            int d  = t & 127;
            int pj = t >> 7;
            float f0 = stF[(size_t)(2*pj    )*STS_ + d];
            float f1 = stF[(size_t)(2*pj + 1)*STS_ + d];
            uint32_t hi, lo;
            split2(f0, f1, hi, lo);
            *(uint2*)(sV + (size_t)d*VS + pj*2) = make_uint2(hi, lo);
        }

        bool active = (kt*64 <= row_max);
        float s[8][4] = {};
        if (active) {
            #pragma unroll
            for (int ks = 0; ks < 8; ks++) {
                uint2 qa0 = *(const uint2*)(sQ + (size_t)(m0+gid  )*QS + (8*ks+qd  )*2);
                uint2 qa1 = *(const uint2*)(sQ + (size_t)(m0+gid+8)*QS + (8*ks+qd  )*2);
                uint2 qa2 = *(const uint2*)(sQ + (size_t)(m0+gid  )*QS + (8*ks+qd+4)*2);
                uint2 qa3 = *(const uint2*)(sQ + (size_t)(m0+gid+8)*QS + (8*ks+qd+4)*2);
                uint32_t ah[4] = {qa0.x, qa1.x, qa2.x, qa3.x};
                uint32_t al[4] = {qa0.y, qa1.y, qa2.y, qa3.y};
                #pragma unroll
                for (int nt = 0; nt < 8; nt++) {
                    uint2 kb0 = *(const uint2*)(sK + (size_t)(nt*8+gid)*KS + (8*ks+qd  )*2);
                    uint2 kb1 = *(const uint2*)(sK + (size_t)(nt*8+gid)*KS + (8*ks+qd+4)*2);
                    mma3b(s[nt], ah, al, kb0.x, kb1.x, kb0.y, kb1.y);
                }
            }

            if (kt*64 + 63 > row_min) {
                int rA = row_min + gid, rB = rA + 8;
                #pragma unroll
                for (int nt = 0; nt < 8; nt++) {
                    int c0 = kt*64 + nt*8 + 2*qd;
                    if (c0     > rA) s[nt][0] = -1e30f;
                    if (c0 + 1 > rA) s[nt][1] = -1e30f;
                    if (c0     > rB) s[nt][2] = -1e30f;
                    if (c0 + 1 > rB) s[nt][3] = -1e30f;
                }
            }

            float mA = -1e30f, mB = -1e30f;
            #pragma unroll
            for (int nt = 0; nt < 8; nt++) {
                mA = fmaxf(mA, fmaxf(s[nt][0], s[nt][1]));
                mB = fmaxf(mB, fmaxf(s[nt][2], s[nt][3]));
            }
            mA = fmaxf(mA, __shfl_xor_sync(0xffffffffu, mA, 1));
            mA = fmaxf(mA, __shfl_xor_sync(0xffffffffu, mA, 2));
            mB = fmaxf(mB, __shfl_xor_sync(0xffffffffu, mB, 1));
            mB = fmaxf(mB, __shfl_xor_sync(0xffffffffu, mB, 2));
            float newmA = fmaxf(miA, mA), newmB = fmaxf(miB, mB);
            float alA = __expf(miA - newmA), alB = __expf(miB - newmB);
            float sumA = 0.f, sumB = 0.f;
            #pragma unroll
            for (int nt = 0; nt < 8; nt++) {
                s[nt][0] = __expf(s[nt][0] - newmA);
                s[nt][1] = __expf(s[nt][1] - newmA);
                s[nt][2] = __expf(s[nt][2] - newmB);
                s[nt][3] = __expf(s[nt][3] - newmB);
                sumA += s[nt][0] + s[nt][1];
                sumB += s[nt][2] + s[nt][3];
            }
            sumA += __shfl_xor_sync(0xffffffffu, sumA, 1);
            sumA += __shfl_xor_sync(0xffffffffu, sumA, 2);
            sumB += __shfl_xor_sync(0xffffffffu, sumB, 1);
            sumB += __shfl_xor_sync(0xffffffffu, sumB, 2);
            liA = liA*alA + sumA;  miA = newmA;
            liB = liB*alB + sumB;  miB = newmB;

            #pragma unroll
            for (int nt = 0; nt < 16; nt++) {
                o[nt][0] *= alA; o[nt][1] *= alA;
                o[nt][2] *= alB; o[nt][3] *= alB;
            }
        }
        __syncthreads();

        if (active) {
            #pragma unroll
            for (int nt = 0; nt < 8; nt++) {
                uint32_t hA, lA, hB, lB;
                split2(s[nt][0], s[nt][1], hA, lA);
                split2(s[nt][2], s[nt][3], hB, lB);
                *(uint2*)(sP + (size_t)(m0+gid  )*PS + (nt*4+qd)*2) = make_uint2(hA, lA);
                *(uint2*)(sP + (size_t)(m0+gid+8)*PS + (nt*4+qd)*2) = make_uint2(hB, lB);
            }
            __syncwarp();

            #pragma unroll
            for (int ks = 0; ks < 4; ks++) {
                uint2 pa0 = *(const uint2*)(sP + (size_t)(m0+gid  )*PS + (8*ks+qd  )*2);
                uint2 pa1 = *(const uint2*)(sP + (size_t)(m0+gid+8)*PS + (8*ks+qd  )*2);
                uint2 pa2 = *(const uint2*)(sP + (size_t)(m0+gid  )*PS + (8*ks+qd+4)*2);
                uint2 pa3 = *(const uint2*)(sP + (size_t)(m0+gid+8)*PS + (8*ks+qd+4)*2);
                uint32_t ph[4] = {pa0.x, pa1.x, pa2.x, pa3.x};
                uint32_t pl[4] = {pa0.y, pa1.y, pa2.y, pa3.y};
                #pragma unroll
                for (int nt = 0; nt < 16; nt++) {
                    uint2 vb0 = *(const uint2*)(sV + (size_t)(nt*8+gid)*VS + (8*ks+qd  )*2);
                    uint2 vb1 = *(const uint2*)(sV + (size_t)(nt*8+gid)*VS + (8*ks+qd+4)*2);
                    mma3b(o[nt], ph, pl, vb0.x, vb1.x, vb0.y, vb1.y);
                }
            }
        }
        __syncthreads();
    }

    float invA = 1.0f / liA, invB = 1.0f / liB;
    float* Og = g_ao + ((size_t)b*SEQ + (size_t)qt*128)*DIM + (size_t)h*HD;
    #pragma unroll
    for (int nt = 0; nt < 16; nt++) {
        int c = nt*8 + 2*qd;
        float2 vA = make_float2(o[nt][0]*invA, o[nt][1]*invA);
        float2 vB = make_float2(o[nt][2]*invB, o[nt][3]*invB);
        *(float2*)(Og + (size_t)(m0 + gid)    *DIM + c) = vA;
        *(float2*)(Og + (size_t)(m0 + gid + 8)*DIM + c) = vB;
    }
}

/* ========================= launch ========================= */
extern "C" void kernel_launch(void* const* d_in, const int* in_sizes, int n_in,
                              void* d_out, int out_size)
{
    const float* x  = (const float*)d_in[0];
    const float* wq = (const float*)d_in[1];
    const float* wk = (const float*)d_in[2];
    const float* wv = (const float*)d_in[3];
    const float* wo = (const float*)d_in[4];
    const float* Sq = (const float*)d_in[5];
    const float* Sk = (const float*)d_in[6];
    const float* Sv = (const float*)d_in[7];
    const float* So = (const float*)d_in[8];
    const float* fr = (const float*)d_in[9];
    float* out = (float*)d_out;

    cudaFuncSetAttribute(k_flash, cudaFuncAttributeMaxDynamicSharedMemorySize,
                         FLASH_SMEM);
    cudaFuncSetAttribute(k_gemm_mma, cudaFuncAttributeMaxDynamicSharedMemorySize,
                         GEMM_SMEM);

    uint32_t* dSB;  cudaGetSymbolAddress((void**)&dSB,  g_SB);
    float*    dAS;  cudaGetSymbolAddress((void**)&dAS,  g_AS);
    float*    dASo; cudaGetSymbolAddress((void**)&dASo, g_ASo);
    float*    dTq;  cudaGetSymbolAddress((void**)&dTq,  g_Tq);
    float*    dTk;  cudaGetSymbolAddress((void**)&dTk,  g_Tk);
    float*    dTv;  cudaGetSymbolAddress((void**)&dTv,  g_Tv);
    float*    dTo;  cudaGetSymbolAddress((void**)&dTo,  g_To);
    float*    dAo;  cudaGetSymbolAddress((void**)&dAo,  g_ao);

    dim3 blk(256);
    const long SBw  = 64L*2048;            /* words per (which,b) B matrix */
    const long SBwb = (long)BATCH*SBw;     /* words per which */

    /* pre-split sketches into MMA-B layout */
    k_splitS<<<2048, blk>>>(Sq, Sk, Sv, So);

    /* all 7 pre-attention GEMMs in ONE launch: jobs 0-2 AS(q,k,v), 3-6 T */
    GemmJobs J = {};
    const float* As[7]    = {x, x, x, wq, wk, wv, wo};
    long sAbs[7]          = {(long)SEQ*DIM, (long)SEQ*DIM, (long)SEQ*DIM, 0, 0, 0, 0};
    int  whichB[7]        = {0, 1, 2, 0, 1, 2, 3};
    float* Cs[7]          = {dAS + 0L*BATCH*SEQ*SK, dAS + 1L*BATCH*SEQ*SK,
                             dAS + 2L*BATCH*SEQ*SK, dTq, dTk, dTv, dTo};
    long sCbs[7]          = {(long)SEQ*SK, (long)SEQ*SK, (long)SEQ*SK,
                             (long)DIM*SK, (long)KVD*SK, (long)KVD*SK, (long)DIM*SK};
    int  mt[7]            = {16, 16, 16, 16, 8, 8, 16};
    float al[7]           = {1.0f/SK, 1.0f/SK, 1.0f/SK, 1.0f, 1.0f, 1.0f, 1.0f};
    for (int i = 0; i < 7; i++) {
        J.A[i] = As[i]; J.sAb[i] = sAbs[i];
        J.B[i] = dSB + (long)whichB[i]*SBwb; J.sBb[i] = SBw;
        J.C[i] = Cs[i]; J.sCb[i] = sCbs[i];
        J.mtiles[i] = mt[i]; J.alpha[i] = al[i];
    }
    k_gemm_mma<<<dim3(16, 7, BATCH), blk, GEMM_SMEM>>>(J);

    /* q/k/v projections (+RoPE, layout to [b,h,s,d]) */
    k_proj<<<dim3(32, 32, BATCH), blk>>>(fr, out, 0);
    k_proj<<<dim3(32, 16, BATCH), blk>>>(fr, out, 1);
    k_proj<<<dim3(32, 16, BATCH), blk>>>(fr, out, 2);

    /* causal flash attention (2-term bf16 split, m16n8k16) -> g_ao */
    k_flash<<<dim3(SEQ/128, NH, BATCH), blk, FLASH_SMEM>>>();

    /* AS_o = attn_out @ So / 64  (same kernel, 1 job) */
    GemmJobs J2 = {};
    J2.A[0] = dAo;  J2.sAb[0] = (long)SEQ*DIM;
    J2.B[0] = dSB + 3L*SBwb; J2.sBb[0] = SBw;
    J2.C[0] = dASo; J2.sCb[0] = (long)SEQ*SK;
    J2.mtiles[0] = 16; J2.alpha[0] = 1.0f/SK;
    k_gemm_mma<<<dim3(16, 1, BATCH), blk, GEMM_SMEM>>>(J2);

    /* final = AS_o @ To^T -> d_out */
    k_proj<<<dim3(32, 32, BATCH), blk>>>(fr, out, 3);
}